// round 14
// baseline (speedup 1.0000x reference)
#include <cuda_runtime.h>
#include <cuda_fp16.h>
#include <mma.h>
#include <cstdint>

using namespace nvcuda;

#define B_TOK 1024
#define DDIM  768
#define FDIM  24576
#define KTOP  64
#define CONN  32

// ---------------- scratch (device globals: no allocation allowed) ----------------
// Device globals are ONLY referenced from device code (host-side &global is the
// host shadow symbol — the bug behind rounds 4/5/6/8/11).
__device__ float g_pre[(size_t)B_TOK * FDIM];
__device__ float g_WupT[(size_t)FDIM * DDIM];        // W_dec_up^T   [F, D]
__device__ float g_WdownT[(size_t)FDIM * DDIM];      // W_dec_down^T [F, D]
__device__ __align__(16) __half g_Xh[(size_t)B_TOK * DDIM];
__device__ __align__(16) __half g_Xm[(size_t)B_TOK * DDIM];
__device__ __align__(16) __half g_Wh[(size_t)FDIM * DDIM];
__device__ __align__(16) __half g_Wm[(size_t)FDIM * DDIM];
__device__ float g_upvals[B_TOK * KTOP];
__device__ int   g_upidx[B_TOK * KTOP];
__device__ float g_downvals[B_TOK * KTOP];
__device__ int   g_downidx[B_TOK * KTOP];
__device__ float g_approx[B_TOK * KTOP];

// ---------------- split fp32 -> planar fp16 hi/mid (PROVEN R12) ----------------
__global__ void split_x_kernel(const float* __restrict__ src, const float* __restrict__ b_dec,
                               int n8)
{
    int i = blockIdx.x * blockDim.x + threadIdx.x;
    if (i >= n8) return;
    int col = (i * 8) % DDIM;
    float4 a = ((const float4*)src)[i * 2];
    float4 b = ((const float4*)src)[i * 2 + 1];
    float4 c = *(const float4*)(b_dec + col);
    float4 d = *(const float4*)(b_dec + col + 4);
    float f[8] = {a.x - c.x, a.y - c.y, a.z - c.z, a.w - c.w,
                  b.x - d.x, b.y - d.y, b.z - d.z, b.w - d.w};
    unsigned short hs[8], ms[8];
#pragma unroll
    for (int j = 0; j < 8; j++) {
        float fs = f[j] * 64.f;
        __half h = __float2half_rn(fs);
        hs[j] = __half_as_ushort(h);
        ms[j] = __half_as_ushort(__float2half_rn(fs - __half2float(h)));
    }
    uint4 hv, mv;
    hv.x = hs[0] | ((unsigned)hs[1] << 16); hv.y = hs[2] | ((unsigned)hs[3] << 16);
    hv.z = hs[4] | ((unsigned)hs[5] << 16); hv.w = hs[6] | ((unsigned)hs[7] << 16);
    mv.x = ms[0] | ((unsigned)ms[1] << 16); mv.y = ms[2] | ((unsigned)ms[3] << 16);
    mv.z = ms[4] | ((unsigned)ms[5] << 16); mv.w = ms[6] | ((unsigned)ms[7] << 16);
    ((uint4*)g_Xh)[i] = hv;
    ((uint4*)g_Xm)[i] = mv;
}

__global__ void split_w_kernel(const float* __restrict__ src, int n8)
{
    int i = blockIdx.x * blockDim.x + threadIdx.x;
    if (i >= n8) return;
    float4 a = ((const float4*)src)[i * 2];
    float4 b = ((const float4*)src)[i * 2 + 1];
    float f[8] = {a.x, a.y, a.z, a.w, b.x, b.y, b.z, b.w};
    unsigned short hs[8], ms[8];
#pragma unroll
    for (int j = 0; j < 8; j++) {
        float fs = f[j] * 64.f;
        __half h = __float2half_rn(fs);
        hs[j] = __half_as_ushort(h);
        ms[j] = __half_as_ushort(__float2half_rn(fs - __half2float(h)));
    }
    uint4 hv, mv;
    hv.x = hs[0] | ((unsigned)hs[1] << 16); hv.y = hs[2] | ((unsigned)hs[3] << 16);
    hv.z = hs[4] | ((unsigned)hs[5] << 16); hv.w = hs[6] | ((unsigned)hs[7] << 16);
    mv.x = ms[0] | ((unsigned)ms[1] << 16); mv.y = ms[2] | ((unsigned)ms[3] << 16);
    mv.z = ms[4] | ((unsigned)ms[5] << 16); mv.w = ms[6] | ((unsigned)ms[7] << 16);
    ((uint4*)g_Wh)[i] = hv;
    ((uint4*)g_Wm)[i] = mv;
}

// ---------------- transpose W_dec [D, F] -> [F, D], float4 both sides ----------------
// store-side bank check: addr (4c+i)*33 + r -> mod 32 = 4c + i + r, distinct per warp.
__global__ void transpose_kernel(const float* __restrict__ in, int which)
{
    __shared__ float tile[32][33];
    float* out = (which == 0) ? g_WupT : g_WdownT;
    int f0 = blockIdx.x * 32;
    int d0 = blockIdx.y * 32;
    int t = threadIdx.x;            // 256 threads
    int r = t >> 3, c = t & 7;

    float4 v = *(const float4*)(in + (size_t)(d0 + r) * FDIM + f0 + 4 * c);
    tile[r][4 * c + 0] = v.x;
    tile[r][4 * c + 1] = v.y;
    tile[r][4 * c + 2] = v.z;
    tile[r][4 * c + 3] = v.w;
    __syncthreads();

    float4 o;
    o.x = tile[4 * c + 0][r];
    o.y = tile[4 * c + 1][r];
    o.z = tile[4 * c + 2][r];
    o.w = tile[4 * c + 3][r];
    *(float4*)(out + (size_t)(f0 + r) * DDIM + d0 + 4 * c) = o;
}

// ---------------- WMMA encode GEMM, BK=16, DOUBLE-BUFFERED (math PROVEN R12) ----------------
// pre = relu( (1/4096) * [XhWh + XhWm + XmWh] + b_enc )
#define TP2   24                 // halves per SMEM row (48 B)
#define PLANE (128 * TP2)        // halves per plane (6144 B)
#define SP    24                 // staging pitch in floats

__global__ __launch_bounds__(256, 2)
void gemm_wmma_kernel(const float* __restrict__ b_enc)
{
    __shared__ __align__(16) __half sbuf[2][4 * PLANE];   // 2 x 24576 B = 48 KB exactly

    const int tid = threadIdx.x;
    const int wid = tid >> 5, lane = tid & 31;
    const int wm = wid >> 2, wn = wid & 3;     // warp tile: rows [wm*64,+64), cols [wn*32,+32)
    const int bm = blockIdx.x * 128;           // over B
    const int bn = blockIdx.y * 128;           // over F

    const int lm = tid >> 1, lq = (tid & 1) * 8;   // loader: row lm, halves [lq, lq+8)

    wmma::fragment<wmma::accumulator, 16, 16, 16, float> c[4][2];
#pragma unroll
    for (int mf = 0; mf < 4; mf++)
#pragma unroll
        for (int nf = 0; nf < 2; nf++)
            wmma::fill_fragment(c[mf][nf], 0.f);

    uint4 rxh, rxm, rwh, rwm;   // prefetch registers
    auto load_regs = [&](int k0) {
        size_t xo = (size_t)(bm + lm) * DDIM + k0 + lq;
        size_t wo = (size_t)(bn + lm) * DDIM + k0 + lq;
        rxh = *(const uint4*)(g_Xh + xo);
        rxm = *(const uint4*)(g_Xm + xo);
        rwh = *(const uint4*)(g_Wh + wo);
        rwm = *(const uint4*)(g_Wm + wo);
    };
    auto store_smem = [&](int b) {
        __half* base = sbuf[b];
        *(uint4*)(base + 0 * PLANE + lm * TP2 + lq) = rxh;
        *(uint4*)(base + 1 * PLANE + lm * TP2 + lq) = rxm;
        *(uint4*)(base + 2 * PLANE + lm * TP2 + lq) = rwh;
        *(uint4*)(base + 3 * PLANE + lm * TP2 + lq) = rwm;
    };

    load_regs(0);
    store_smem(0);
    __syncthreads();

    const int NSTEP = DDIM / 16;   // 48
    for (int s = 0; s < NSTEP; s++) {
        if (s + 1 < NSTEP) load_regs((s + 1) * 16);   // global loads overlap compute

        const __half* base = sbuf[s & 1];
        const __half* Ah = base;
        const __half* Am = base + PLANE;
        const __half* Wh = base + 2 * PLANE;
        const __half* Wm = base + 3 * PLANE;

        wmma::fragment<wmma::matrix_a, 16, 16, 16, __half, wmma::row_major> ah[4], am[4];
#pragma unroll
        for (int mf = 0; mf < 4; mf++) {
            wmma::load_matrix_sync(ah[mf], Ah + (wm * 64 + mf * 16) * TP2, TP2);
            wmma::load_matrix_sync(am[mf], Am + (wm * 64 + mf * 16) * TP2, TP2);
        }
#pragma unroll
        for (int nf = 0; nf < 2; nf++) {
            wmma::fragment<wmma::matrix_b, 16, 16, 16, __half, wmma::col_major> bh, bm2;
            wmma::load_matrix_sync(bh,  Wh + (wn * 32 + nf * 16) * TP2, TP2);
            wmma::load_matrix_sync(bm2, Wm + (wn * 32 + nf * 16) * TP2, TP2);
#pragma unroll
            for (int mf = 0; mf < 4; mf++) {
                wmma::mma_sync(c[mf][nf], ah[mf], bh,  c[mf][nf]);
                wmma::mma_sync(c[mf][nf], ah[mf], bm2, c[mf][nf]);
                wmma::mma_sync(c[mf][nf], am[mf], bh,  c[mf][nf]);
            }
        }

        if (s + 1 < NSTEP) store_smem((s + 1) & 1);   // other buffer: no pre-sync needed
        __syncthreads();                               // one sync per step
    }

    // ---- epilogue (PROVEN R9 pattern), stage aliased into sbuf (all reads synced) ----
    float* stg = (float*)sbuf + wid * 16 * SP;
    const float inv = 1.f / 4096.f;
    const int r2 = lane >> 1, cq = (lane & 1) * 8;
#pragma unroll
    for (int mf = 0; mf < 4; mf++) {
#pragma unroll
        for (int nf = 0; nf < 2; nf++) {
            wmma::store_matrix_sync(stg, c[mf][nf], SP, wmma::mem_row_major);
            __syncwarp();
            int grow = bm + wm * 64 + mf * 16 + r2;
            int gcol = bn + wn * 32 + nf * 16 + cq;
            float4 s0 = *(const float4*)(stg + r2 * SP + cq);
            float4 s1 = *(const float4*)(stg + r2 * SP + cq + 4);
            float4 o0, o1;
            o0.x = fmaxf(s0.x * inv + b_enc[gcol + 0], 0.f);
            o0.y = fmaxf(s0.y * inv + b_enc[gcol + 1], 0.f);
            o0.z = fmaxf(s0.z * inv + b_enc[gcol + 2], 0.f);
            o0.w = fmaxf(s0.w * inv + b_enc[gcol + 3], 0.f);
            o1.x = fmaxf(s1.x * inv + b_enc[gcol + 4], 0.f);
            o1.y = fmaxf(s1.y * inv + b_enc[gcol + 5], 0.f);
            o1.z = fmaxf(s1.z * inv + b_enc[gcol + 6], 0.f);
            o1.w = fmaxf(s1.w * inv + b_enc[gcol + 7], 0.f);
            *(float4*)(g_pre + (size_t)grow * FDIM + gcol)     = o0;
            *(float4*)(g_pre + (size_t)grow * FDIM + gcol + 4) = o1;
            __syncwarp();
        }
    }
}

// ---------------- exact top-64 radix select, float4 passes (PROVEN R13) ----------------
__global__ void topk_select_kernel(int which)
{
    const int b = blockIdx.x, t = threadIdx.x;   // 512 threads, 12 float4 each
    const float4* row4 = (const float4*)(g_pre + (size_t)b * FDIM);
    __shared__ int   hist[2048];
    __shared__ int   sc[512];
    __shared__ int   sc2[512];
    __shared__ int   s_bstar, s_nabove, s_ncand;
    __shared__ int   cidx[1024];
    __shared__ float cval[1024];

    for (int i = t; i < 2048; i += 512) hist[i] = 0;
    __syncthreads();
    for (int j = 0; j < 12; j++) {
        float4 v = row4[t + (j << 9)];
        if (v.x > 0.f) atomicAdd(&hist[__float_as_uint(v.x) >> 21], 1);
        if (v.y > 0.f) atomicAdd(&hist[__float_as_uint(v.y) >> 21], 1);
        if (v.z > 0.f) atomicAdd(&hist[__float_as_uint(v.z) >> 21], 1);
        if (v.w > 0.f) atomicAdd(&hist[__float_as_uint(v.w) >> 21], 1);
    }
    __syncthreads();
    {
        int s = 0;
#pragma unroll
        for (int i = 0; i < 4; i++) s += hist[t * 4 + i];
        sc[t] = s;
    }
    __syncthreads();
    if (t == 0) {
        int cum = 0, bstar = 0, nab = 0;
        bool found = false;
        for (int s = 511; s >= 0 && !found; s--) {
            int sv = sc[s];
            if (sv == 0) continue;
            if (cum + sv >= KTOP) {
                for (int bi = s * 4 + 3; bi >= s * 4; bi--) {
                    int h = hist[bi];
                    if (cum + h >= KTOP) { bstar = bi; nab = cum; found = true; break; }
                    cum += h;
                }
            } else cum += sv;
        }
        if (!found) { bstar = 0; nab = cum; }
        s_bstar = bstar; s_nabove = nab;
    }
    __syncthreads();
    const unsigned bstar = (unsigned)s_bstar;
    const int nabove = s_nabove;

    float* ov = ((which == 0) ? g_upvals : g_downvals) + b * KTOP;
    int*   oi = ((which == 0) ? g_upidx  : g_downidx)  + b * KTOP;

    int cnt = 0, ccnt = 0;
    for (int j = 0; j < 12; j++) {
        float4 v = row4[t + (j << 9)];
        float vv[4] = {v.x, v.y, v.z, v.w};
#pragma unroll
        for (int cc2 = 0; cc2 < 4; cc2++) {
            if (vv[cc2] > 0.f) {
                unsigned bin = __float_as_uint(vv[cc2]) >> 21;
                cnt  += (bin > bstar);
                ccnt += (bin == bstar);
            }
        }
    }
    sc[t] = cnt; sc2[t] = ccnt;
    __syncthreads();
    for (int o = 1; o < 512; o <<= 1) {
        int v1 = (t >= o) ? sc[t - o] : 0;
        int v2 = (t >= o) ? sc2[t - o] : 0;
        __syncthreads();
        sc[t] += v1; sc2[t] += v2;
        __syncthreads();
    }
    if (t == 511) s_ncand = (sc2[511] < 1024) ? sc2[511] : 1024;

    {
        int pos = sc[t] - cnt, cpos = sc2[t] - ccnt;
        int left = cnt + ccnt;
        for (int j = 0; j < 12 && left > 0; j++) {
            int base = (t + (j << 9)) * 4;
            float4 v = row4[t + (j << 9)];
            float vv[4] = {v.x, v.y, v.z, v.w};
#pragma unroll
            for (int cc2 = 0; cc2 < 4; cc2++) {
                if (vv[cc2] > 0.f) {
                    unsigned bin = __float_as_uint(vv[cc2]) >> 21;
                    if (bin > bstar) {
                        ov[pos] = vv[cc2]; oi[pos] = base + cc2; pos++; left--;
                    } else if (bin == bstar) {
                        if (cpos < 1024) { cidx[cpos] = base + cc2; cval[cpos] = vv[cc2]; }
                        cpos++; left--;
                    }
                }
            }
        }
    }
    __syncthreads();

    if (t < 32) {
        const int need = KTOP - nabove;
        const int ncand = s_ncand;
        for (int r = 0; r < need; r++) {
            float bv = -1.f; int bidx = 0x7fffffff; int bslot = -1;
            for (int i = t; i < ncand; i += 32) {
                int ix = cidx[i];
                if (ix >= 0) {
                    float v = cval[i];
                    if (v > bv || (v == bv && ix < bidx)) { bv = v; bidx = ix; bslot = i; }
                }
            }
#pragma unroll
            for (int o = 16; o > 0; o >>= 1) {
                float v2 = __shfl_down_sync(0xffffffffu, bv, o);
                int   i2 = __shfl_down_sync(0xffffffffu, bidx, o);
                int   s2 = __shfl_down_sync(0xffffffffu, bslot, o);
                if (v2 > bv || (v2 == bv && i2 < bidx)) { bv = v2; bidx = i2; bslot = s2; }
            }
            bv = __shfl_sync(0xffffffffu, bv, 0);
            bidx = __shfl_sync(0xffffffffu, bidx, 0);
            bslot = __shfl_sync(0xffffffffu, bslot, 0);
            if (t == 0 && bslot >= 0) {
                ov[nabove + r] = bv; oi[nabove + r] = bidx; cidx[bslot] = -1;
            }
            __syncwarp();
        }
    }
}

// ---------------- contributions: approx_acts[b,kd] (PROVEN) ----------------
__global__ void contrib_kernel(const int* __restrict__ conn,
                               const float* __restrict__ W_enc_down)
{
    const int b = blockIdx.x;
    const int w = threadIdx.x >> 5, lane = threadIdx.x & 31;
    __shared__ int   s_ui[KTOP];
    __shared__ float s_uv[KTOP];
    if (threadIdx.x < KTOP) {
        s_ui[threadIdx.x] = g_upidx[b * KTOP + threadIdx.x];
        s_uv[threadIdx.x] = g_upvals[b * KTOP + threadIdx.x];
    }
    __syncthreads();

    for (int kd = w; kd < KTOP; kd += 8) {
        int fd = g_downidx[b * KTOP + kd];
        int ci = conn[(size_t)fd * CONN + lane];

        float partial = 0.f;
        bool loaded = false;
        float er[24];
        for (int ku = 0; ku < KTOP; ku++) {
            int fu = s_ui[ku];
            unsigned m = __ballot_sync(0xffffffffu, ci == fu);
            if (m) {
                if (!loaded) {
#pragma unroll
                    for (int i = 0; i < 24; i++)
                        er[i] = W_enc_down[(size_t)fd * DDIM + lane + i * 32];
                    loaded = true;
                }
                float cntf = (float)__popc(m);
                const float* up = g_WupT + (size_t)fu * DDIM + lane;
                float dot = 0.f;
#pragma unroll
                for (int i = 0; i < 24; i++) dot += er[i] * up[i * 32];
                partial += dot * cntf * s_uv[ku];
            }
        }
#pragma unroll
        for (int o = 16; o > 0; o >>= 1)
            partial += __shfl_down_sync(0xffffffffu, partial, o);
        if (lane == 0) g_approx[b * KTOP + kd] = partial;
    }
}

// ---------------- sparse decode (PROVEN) ----------------
__global__ void recon_kernel(int which, const float* __restrict__ b_dec, float* __restrict__ out)
{
    const int b = blockIdx.x;
    const int t = threadIdx.x;  // 256
    __shared__ float sv[KTOP];
    __shared__ int   si[KTOP];
    if (t < KTOP) {
        if (which == 0) { sv[t] = g_upvals[b * KTOP + t]; si[t] = g_upidx[b * KTOP + t]; }
        else            { sv[t] = g_approx[b * KTOP + t]; si[t] = g_downidx[b * KTOP + t]; }
    }
    __syncthreads();
    const float* WT = (which == 0) ? g_WupT : g_WdownT;

    float a0 = b_dec[t], a1 = b_dec[t + 256], a2 = b_dec[t + 512];
    for (int k = 0; k < KTOP; k++) {
        const float* p = WT + (size_t)si[k] * DDIM + t;
        float v = sv[k];
        a0 += v * p[0];
        a1 += v * p[256];
        a2 += v * p[512];
    }
    size_t o = (size_t)b * DDIM + t;
    out[o]       = a0;
    out[o + 256] = a1;
    out[o + 512] = a2;
}

// ---------------- launch ----------------
extern "C" void kernel_launch(void* const* d_in, const int* in_sizes, int n_in,
                              void* d_out, int out_size)
{
    (void)in_sizes; (void)n_in; (void)out_size;
    const float* x_up       = (const float*)d_in[0];
    const float* x_down     = (const float*)d_in[1];
    const float* W_enc_up   = (const float*)d_in[2];
    const float* b_enc_up   = (const float*)d_in[3];
    const float* W_dec_up   = (const float*)d_in[4];
    const float* b_dec_up   = (const float*)d_in[5];
    const float* W_enc_down = (const float*)d_in[6];
    const float* b_enc_down = (const float*)d_in[7];
    const float* W_dec_down = (const float*)d_in[8];
    const float* b_dec_down = (const float*)d_in[9];
    const int*   connections = (const int*)d_in[10];
    float* out = (float*)d_out;

    const int n8w = FDIM * DDIM / 8;   // 2359296
    const int n8x = B_TOK * DDIM / 8;  // 98304
    dim3 gemm_grid(B_TOK / 128, FDIM / 128);   // x: B tiles (8), y: F tiles (192)
    dim3 tr_grid(FDIM / 32, DDIM / 32);

    // ---- upstream ----
    split_w_kernel<<<n8w / 512, 512>>>(W_enc_up, n8w);
    split_x_kernel<<<n8x / 512, 512>>>(x_up, b_dec_up, n8x);
    gemm_wmma_kernel<<<gemm_grid, 256>>>(b_enc_up);
    topk_select_kernel<<<B_TOK, 512>>>(0);
    transpose_kernel<<<tr_grid, 256>>>(W_dec_up, 0);
    recon_kernel<<<B_TOK, 256>>>(0, b_dec_up, out);

    // ---- downstream ----
    split_w_kernel<<<n8w / 512, 512>>>(W_enc_down, n8w);
    split_x_kernel<<<n8x / 512, 512>>>(x_down, b_dec_down, n8x);
    gemm_wmma_kernel<<<gemm_grid, 256>>>(b_enc_down);
    topk_select_kernel<<<B_TOK, 512>>>(1);
    transpose_kernel<<<tr_grid, 256>>>(W_dec_down, 1);
    contrib_kernel<<<B_TOK, 256>>>(connections, W_enc_down);
    recon_kernel<<<B_TOK, 256>>>(1, b_dec_down, out + (size_t)B_TOK * DDIM);
}

// round 15
// speedup vs baseline: 1.0397x; 1.0397x over previous
#include <cuda_runtime.h>
#include <cuda_fp16.h>
#include <mma.h>
#include <cstdint>

using namespace nvcuda;

#define B_TOK 1024
#define DDIM  768
#define FDIM  24576
#define KTOP  64
#define CONN  32

// ---------------- scratch (device globals: no allocation allowed) ----------------
// Device globals are ONLY referenced from device code (host-side &global is the
// host shadow symbol — the bug behind rounds 4/5/6/8/11).
__device__ float g_pre[(size_t)B_TOK * FDIM];
__device__ float g_WupT[(size_t)FDIM * DDIM];        // W_dec_up^T   [F, D]
__device__ float g_WdownT[(size_t)FDIM * DDIM];      // W_dec_down^T [F, D]
__device__ __align__(16) __half g_Xh[(size_t)B_TOK * DDIM];
__device__ __align__(16) __half g_Xm[(size_t)B_TOK * DDIM];
__device__ __align__(16) __half g_Wh[(size_t)FDIM * DDIM];
__device__ __align__(16) __half g_Wm[(size_t)FDIM * DDIM];
__device__ float g_upvals[B_TOK * KTOP];
__device__ int   g_upidx[B_TOK * KTOP];
__device__ float g_downvals[B_TOK * KTOP];
__device__ int   g_downidx[B_TOK * KTOP];
__device__ float g_approx[B_TOK * KTOP];

// ---------------- split fp32 -> planar fp16 hi/mid (PROVEN R12) ----------------
__global__ void split_x_kernel(const float* __restrict__ src, const float* __restrict__ b_dec,
                               int n8)
{
    int i = blockIdx.x * blockDim.x + threadIdx.x;
    if (i >= n8) return;
    int col = (i * 8) % DDIM;
    float4 a = ((const float4*)src)[i * 2];
    float4 b = ((const float4*)src)[i * 2 + 1];
    float4 c = *(const float4*)(b_dec + col);
    float4 d = *(const float4*)(b_dec + col + 4);
    float f[8] = {a.x - c.x, a.y - c.y, a.z - c.z, a.w - c.w,
                  b.x - d.x, b.y - d.y, b.z - d.z, b.w - d.w};
    unsigned short hs[8], ms[8];
#pragma unroll
    for (int j = 0; j < 8; j++) {
        float fs = f[j] * 64.f;
        __half h = __float2half_rn(fs);
        hs[j] = __half_as_ushort(h);
        ms[j] = __half_as_ushort(__float2half_rn(fs - __half2float(h)));
    }
    uint4 hv, mv;
    hv.x = hs[0] | ((unsigned)hs[1] << 16); hv.y = hs[2] | ((unsigned)hs[3] << 16);
    hv.z = hs[4] | ((unsigned)hs[5] << 16); hv.w = hs[6] | ((unsigned)hs[7] << 16);
    mv.x = ms[0] | ((unsigned)ms[1] << 16); mv.y = ms[2] | ((unsigned)ms[3] << 16);
    mv.z = ms[4] | ((unsigned)ms[5] << 16); mv.w = ms[6] | ((unsigned)ms[7] << 16);
    ((uint4*)g_Xh)[i] = hv;
    ((uint4*)g_Xm)[i] = mv;
}

__global__ void split_w_kernel(const float* __restrict__ src, int n8)
{
    int i = blockIdx.x * blockDim.x + threadIdx.x;
    if (i >= n8) return;
    float4 a = ((const float4*)src)[i * 2];
    float4 b = ((const float4*)src)[i * 2 + 1];
    float f[8] = {a.x, a.y, a.z, a.w, b.x, b.y, b.z, b.w};
    unsigned short hs[8], ms[8];
#pragma unroll
    for (int j = 0; j < 8; j++) {
        float fs = f[j] * 64.f;
        __half h = __float2half_rn(fs);
        hs[j] = __half_as_ushort(h);
        ms[j] = __half_as_ushort(__float2half_rn(fs - __half2float(h)));
    }
    uint4 hv, mv;
    hv.x = hs[0] | ((unsigned)hs[1] << 16); hv.y = hs[2] | ((unsigned)hs[3] << 16);
    hv.z = hs[4] | ((unsigned)hs[5] << 16); hv.w = hs[6] | ((unsigned)hs[7] << 16);
    mv.x = ms[0] | ((unsigned)ms[1] << 16); mv.y = ms[2] | ((unsigned)ms[3] << 16);
    mv.z = ms[4] | ((unsigned)ms[5] << 16); mv.w = ms[6] | ((unsigned)ms[7] << 16);
    ((uint4*)g_Wh)[i] = hv;
    ((uint4*)g_Wm)[i] = mv;
}

// ---------------- transpose W_dec [D, F] -> [F, D], float4 both sides (PROVEN R14) ----------------
__global__ void transpose_kernel(const float* __restrict__ in, int which)
{
    __shared__ float tile[32][33];
    float* out = (which == 0) ? g_WupT : g_WdownT;
    int f0 = blockIdx.x * 32;
    int d0 = blockIdx.y * 32;
    int t = threadIdx.x;            // 256 threads
    int r = t >> 3, c = t & 7;

    float4 v = *(const float4*)(in + (size_t)(d0 + r) * FDIM + f0 + 4 * c);
    tile[r][4 * c + 0] = v.x;
    tile[r][4 * c + 1] = v.y;
    tile[r][4 * c + 2] = v.z;
    tile[r][4 * c + 3] = v.w;
    __syncthreads();

    float4 o;
    o.x = tile[4 * c + 0][r];
    o.y = tile[4 * c + 1][r];
    o.z = tile[4 * c + 2][r];
    o.w = tile[4 * c + 3][r];
    *(float4*)(out + (size_t)(f0 + r) * DDIM + d0 + 4 * c) = o;
}

// ---------------- WMMA encode GEMM on pre-split fp16 planes (PROVEN R12, verbatim) ----------------
// pre = relu( (1/4096) * [XhWh + XhWm + XmWh] + b_enc ); A row_major, B col_major,
// SMEM k-contiguous rows (pitch 24 halves).
#define TP2 24    // halves per SMEM row (48 B)
#define SP  24    // staging pitch in floats

__global__ __launch_bounds__(256, 2)
void gemm_wmma_kernel(const float* __restrict__ b_enc)
{
    __shared__ __align__(16) __half Ah[128][TP2];
    __shared__ __align__(16) __half Am[128][TP2];
    __shared__ __align__(16) __half Wh[128][TP2];
    __shared__ __align__(16) __half Wm[128][TP2];
    __shared__ __align__(16) float  stage[8][16 * SP];

    const int tid = threadIdx.x;
    const int wid = tid >> 5, lane = tid & 31;
    const int wm = wid >> 2, wn = wid & 3;     // warp tile: rows [wm*64,+64), cols [wn*32,+32)
    const int bm = blockIdx.x * 128;           // over B
    const int bn = blockIdx.y * 128;           // over F

    const int lm = tid >> 1, lq = (tid & 1) * 8;   // loader: row lm, halves [lq, lq+8)

    wmma::fragment<wmma::accumulator, 16, 16, 16, float> c[4][2];
#pragma unroll
    for (int mf = 0; mf < 4; mf++)
#pragma unroll
        for (int nf = 0; nf < 2; nf++)
            wmma::fill_fragment(c[mf][nf], 0.f);

    uint4 rxh, rxm, rwh, rwm;   // prefetch registers
    auto load_regs = [&](int k0) {
        size_t xo = (size_t)(bm + lm) * DDIM + k0 + lq;
        size_t wo = (size_t)(bn + lm) * DDIM + k0 + lq;
        rxh = *(const uint4*)(g_Xh + xo);
        rxm = *(const uint4*)(g_Xm + xo);
        rwh = *(const uint4*)(g_Wh + wo);
        rwm = *(const uint4*)(g_Wm + wo);
    };
    auto store_smem = [&]() {
        *(uint4*)&Ah[lm][lq] = rxh;
        *(uint4*)&Am[lm][lq] = rxm;
        *(uint4*)&Wh[lm][lq] = rwh;
        *(uint4*)&Wm[lm][lq] = rwm;
    };

    load_regs(0);
    for (int k0 = 0; k0 < DDIM; k0 += 16) {
        store_smem();
        __syncthreads();
        if (k0 + 16 < DDIM) load_regs(k0 + 16);   // overlap next loads with compute

        wmma::fragment<wmma::matrix_a, 16, 16, 16, __half, wmma::row_major> ah[4], am[4];
#pragma unroll
        for (int mf = 0; mf < 4; mf++) {
            wmma::load_matrix_sync(ah[mf], &Ah[wm * 64 + mf * 16][0], TP2);
            wmma::load_matrix_sync(am[mf], &Am[wm * 64 + mf * 16][0], TP2);
        }
#pragma unroll
        for (int nf = 0; nf < 2; nf++) {
            wmma::fragment<wmma::matrix_b, 16, 16, 16, __half, wmma::col_major> bh, bm2;
            wmma::load_matrix_sync(bh,  &Wh[wn * 32 + nf * 16][0], TP2);
            wmma::load_matrix_sync(bm2, &Wm[wn * 32 + nf * 16][0], TP2);
#pragma unroll
            for (int mf = 0; mf < 4; mf++) {
                wmma::mma_sync(c[mf][nf], ah[mf], bh,  c[mf][nf]);
                wmma::mma_sync(c[mf][nf], ah[mf], bm2, c[mf][nf]);
                wmma::mma_sync(c[mf][nf], am[mf], bh,  c[mf][nf]);
            }
        }
        __syncthreads();
    }

    // ---- epilogue (PROVEN R9) ----
    const float inv = 1.f / 4096.f;
    const int r2 = lane >> 1, cq = (lane & 1) * 8;
#pragma unroll
    for (int mf = 0; mf < 4; mf++) {
#pragma unroll
        for (int nf = 0; nf < 2; nf++) {
            wmma::store_matrix_sync(&stage[wid][0], c[mf][nf], SP, wmma::mem_row_major);
            __syncwarp();
            int grow = bm + wm * 64 + mf * 16 + r2;
            int gcol = bn + wn * 32 + nf * 16 + cq;
            float4 s0 = *(const float4*)(&stage[wid][r2 * SP + cq]);
            float4 s1 = *(const float4*)(&stage[wid][r2 * SP + cq + 4]);
            float4 o0, o1;
            o0.x = fmaxf(s0.x * inv + b_enc[gcol + 0], 0.f);
            o0.y = fmaxf(s0.y * inv + b_enc[gcol + 1], 0.f);
            o0.z = fmaxf(s0.z * inv + b_enc[gcol + 2], 0.f);
            o0.w = fmaxf(s0.w * inv + b_enc[gcol + 3], 0.f);
            o1.x = fmaxf(s1.x * inv + b_enc[gcol + 4], 0.f);
            o1.y = fmaxf(s1.y * inv + b_enc[gcol + 5], 0.f);
            o1.z = fmaxf(s1.z * inv + b_enc[gcol + 6], 0.f);
            o1.w = fmaxf(s1.w * inv + b_enc[gcol + 7], 0.f);
            *(float4*)(g_pre + (size_t)grow * FDIM + gcol)     = o0;
            *(float4*)(g_pre + (size_t)grow * FDIM + gcol + 4) = o1;
            __syncwarp();
        }
    }
}

// ---------------- exact top-64 radix select, float4 passes (PROVEN R13) ----------------
__global__ void topk_select_kernel(int which)
{
    const int b = blockIdx.x, t = threadIdx.x;   // 512 threads, 12 float4 each
    const float4* row4 = (const float4*)(g_pre + (size_t)b * FDIM);
    __shared__ int   hist[2048];
    __shared__ int   sc[512];
    __shared__ int   sc2[512];
    __shared__ int   s_bstar, s_nabove, s_ncand;
    __shared__ int   cidx[1024];
    __shared__ float cval[1024];

    for (int i = t; i < 2048; i += 512) hist[i] = 0;
    __syncthreads();
    for (int j = 0; j < 12; j++) {
        float4 v = row4[t + (j << 9)];
        if (v.x > 0.f) atomicAdd(&hist[__float_as_uint(v.x) >> 21], 1);
        if (v.y > 0.f) atomicAdd(&hist[__float_as_uint(v.y) >> 21], 1);
        if (v.z > 0.f) atomicAdd(&hist[__float_as_uint(v.z) >> 21], 1);
        if (v.w > 0.f) atomicAdd(&hist[__float_as_uint(v.w) >> 21], 1);
    }
    __syncthreads();
    {
        int s = 0;
#pragma unroll
        for (int i = 0; i < 4; i++) s += hist[t * 4 + i];
        sc[t] = s;
    }
    __syncthreads();
    if (t == 0) {
        int cum = 0, bstar = 0, nab = 0;
        bool found = false;
        for (int s = 511; s >= 0 && !found; s--) {
            int sv = sc[s];
            if (sv == 0) continue;
            if (cum + sv >= KTOP) {
                for (int bi = s * 4 + 3; bi >= s * 4; bi--) {
                    int h = hist[bi];
                    if (cum + h >= KTOP) { bstar = bi; nab = cum; found = true; break; }
                    cum += h;
                }
            } else cum += sv;
        }
        if (!found) { bstar = 0; nab = cum; }
        s_bstar = bstar; s_nabove = nab;
    }
    __syncthreads();
    const unsigned bstar = (unsigned)s_bstar;
    const int nabove = s_nabove;

    float* ov = ((which == 0) ? g_upvals : g_downvals) + b * KTOP;
    int*   oi = ((which == 0) ? g_upidx  : g_downidx)  + b * KTOP;

    int cnt = 0, ccnt = 0;
    for (int j = 0; j < 12; j++) {
        float4 v = row4[t + (j << 9)];
        float vv[4] = {v.x, v.y, v.z, v.w};
#pragma unroll
        for (int cc2 = 0; cc2 < 4; cc2++) {
            if (vv[cc2] > 0.f) {
                unsigned bin = __float_as_uint(vv[cc2]) >> 21;
                cnt  += (bin > bstar);
                ccnt += (bin == bstar);
            }
        }
    }
    sc[t] = cnt; sc2[t] = ccnt;
    __syncthreads();
    for (int o = 1; o < 512; o <<= 1) {
        int v1 = (t >= o) ? sc[t - o] : 0;
        int v2 = (t >= o) ? sc2[t - o] : 0;
        __syncthreads();
        sc[t] += v1; sc2[t] += v2;
        __syncthreads();
    }
    if (t == 511) s_ncand = (sc2[511] < 1024) ? sc2[511] : 1024;

    {
        int pos = sc[t] - cnt, cpos = sc2[t] - ccnt;
        int left = cnt + ccnt;
        for (int j = 0; j < 12 && left > 0; j++) {
            int base = (t + (j << 9)) * 4;
            float4 v = row4[t + (j << 9)];
            float vv[4] = {v.x, v.y, v.z, v.w};
#pragma unroll
            for (int cc2 = 0; cc2 < 4; cc2++) {
                if (vv[cc2] > 0.f) {
                    unsigned bin = __float_as_uint(vv[cc2]) >> 21;
                    if (bin > bstar) {
                        ov[pos] = vv[cc2]; oi[pos] = base + cc2; pos++; left--;
                    } else if (bin == bstar) {
                        if (cpos < 1024) { cidx[cpos] = base + cc2; cval[cpos] = vv[cc2]; }
                        cpos++; left--;
                    }
                }
            }
        }
    }
    __syncthreads();

    if (t < 32) {
        const int need = KTOP - nabove;
        const int ncand = s_ncand;
        for (int r = 0; r < need; r++) {
            float bv = -1.f; int bidx = 0x7fffffff; int bslot = -1;
            for (int i = t; i < ncand; i += 32) {
                int ix = cidx[i];
                if (ix >= 0) {
                    float v = cval[i];
                    if (v > bv || (v == bv && ix < bidx)) { bv = v; bidx = ix; bslot = i; }
                }
            }
#pragma unroll
            for (int o = 16; o > 0; o >>= 1) {
                float v2 = __shfl_down_sync(0xffffffffu, bv, o);
                int   i2 = __shfl_down_sync(0xffffffffu, bidx, o);
                int   s2 = __shfl_down_sync(0xffffffffu, bslot, o);
                if (v2 > bv || (v2 == bv && i2 < bidx)) { bv = v2; bidx = i2; bslot = s2; }
            }
            bv = __shfl_sync(0xffffffffu, bv, 0);
            bidx = __shfl_sync(0xffffffffu, bidx, 0);
            bslot = __shfl_sync(0xffffffffu, bslot, 0);
            if (t == 0 && bslot >= 0) {
                ov[nabove + r] = bv; oi[nabove + r] = bidx; cidx[bslot] = -1;
            }
            __syncwarp();
        }
    }
}

// ---------------- contributions: approx_acts[b,kd] (PROVEN) ----------------
__global__ void contrib_kernel(const int* __restrict__ conn,
                               const float* __restrict__ W_enc_down)
{
    const int b = blockIdx.x;
    const int w = threadIdx.x >> 5, lane = threadIdx.x & 31;
    __shared__ int   s_ui[KTOP];
    __shared__ float s_uv[KTOP];
    if (threadIdx.x < KTOP) {
        s_ui[threadIdx.x] = g_upidx[b * KTOP + threadIdx.x];
        s_uv[threadIdx.x] = g_upvals[b * KTOP + threadIdx.x];
    }
    __syncthreads();

    for (int kd = w; kd < KTOP; kd += 8) {
        int fd = g_downidx[b * KTOP + kd];
        int ci = conn[(size_t)fd * CONN + lane];

        float partial = 0.f;
        bool loaded = false;
        float er[24];
        for (int ku = 0; ku < KTOP; ku++) {
            int fu = s_ui[ku];
            unsigned m = __ballot_sync(0xffffffffu, ci == fu);
            if (m) {
                if (!loaded) {
#pragma unroll
                    for (int i = 0; i < 24; i++)
                        er[i] = W_enc_down[(size_t)fd * DDIM + lane + i * 32];
                    loaded = true;
                }
                float cntf = (float)__popc(m);
                const float* up = g_WupT + (size_t)fu * DDIM + lane;
                float dot = 0.f;
#pragma unroll
                for (int i = 0; i < 24; i++) dot += er[i] * up[i * 32];
                partial += dot * cntf * s_uv[ku];
            }
        }
#pragma unroll
        for (int o = 16; o > 0; o >>= 1)
            partial += __shfl_down_sync(0xffffffffu, partial, o);
        if (lane == 0) g_approx[b * KTOP + kd] = partial;
    }
}

// ---------------- sparse decode (PROVEN) ----------------
__global__ void recon_kernel(int which, const float* __restrict__ b_dec, float* __restrict__ out)
{
    const int b = blockIdx.x;
    const int t = threadIdx.x;  // 256
    __shared__ float sv[KTOP];
    __shared__ int   si[KTOP];
    if (t < KTOP) {
        if (which == 0) { sv[t] = g_upvals[b * KTOP + t]; si[t] = g_upidx[b * KTOP + t]; }
        else            { sv[t] = g_approx[b * KTOP + t]; si[t] = g_downidx[b * KTOP + t]; }
    }
    __syncthreads();
    const float* WT = (which == 0) ? g_WupT : g_WdownT;

    float a0 = b_dec[t], a1 = b_dec[t + 256], a2 = b_dec[t + 512];
    for (int k = 0; k < KTOP; k++) {
        const float* p = WT + (size_t)si[k] * DDIM + t;
        float v = sv[k];
        a0 += v * p[0];
        a1 += v * p[256];
        a2 += v * p[512];
    }
    size_t o = (size_t)b * DDIM + t;
    out[o]       = a0;
    out[o + 256] = a1;
    out[o + 512] = a2;
}

// ---------------- launch ----------------
extern "C" void kernel_launch(void* const* d_in, const int* in_sizes, int n_in,
                              void* d_out, int out_size)
{
    (void)in_sizes; (void)n_in; (void)out_size;
    const float* x_up       = (const float*)d_in[0];
    const float* x_down     = (const float*)d_in[1];
    const float* W_enc_up   = (const float*)d_in[2];
    const float* b_enc_up   = (const float*)d_in[3];
    const float* W_dec_up   = (const float*)d_in[4];
    const float* b_dec_up   = (const float*)d_in[5];
    const float* W_enc_down = (const float*)d_in[6];
    const float* b_enc_down = (const float*)d_in[7];
    const float* W_dec_down = (const float*)d_in[8];
    const float* b_dec_down = (const float*)d_in[9];
    const int*   connections = (const int*)d_in[10];
    float* out = (float*)d_out;

    const int n8w = FDIM * DDIM / 8;   // 2359296
    const int n8x = B_TOK * DDIM / 8;  // 98304
    dim3 gemm_grid(B_TOK / 128, FDIM / 128);   // x: B tiles (8), y: F tiles (192)
    dim3 tr_grid(FDIM / 32, DDIM / 32);

    // ---- upstream ----
    split_w_kernel<<<n8w / 512, 512>>>(W_enc_up, n8w);
    split_x_kernel<<<n8x / 512, 512>>>(x_up, b_dec_up, n8x);
    gemm_wmma_kernel<<<gemm_grid, 256>>>(b_enc_up);
    topk_select_kernel<<<B_TOK, 512>>>(0);
    transpose_kernel<<<tr_grid, 256>>>(W_dec_up, 0);
    recon_kernel<<<B_TOK, 256>>>(0, b_dec_up, out);

    // ---- downstream ----
    split_w_kernel<<<n8w / 512, 512>>>(W_enc_down, n8w);
    split_x_kernel<<<n8x / 512, 512>>>(x_down, b_dec_down, n8x);
    gemm_wmma_kernel<<<gemm_grid, 256>>>(b_enc_down);
    topk_select_kernel<<<B_TOK, 512>>>(1);
    transpose_kernel<<<tr_grid, 256>>>(W_dec_down, 1);
    contrib_kernel<<<B_TOK, 256>>>(connections, W_enc_down);
    recon_kernel<<<B_TOK, 256>>>(1, b_dec_down, out + (size_t)B_TOK * DDIM);
}

// round 16
// speedup vs baseline: 1.0690x; 1.0281x over previous
#include <cuda_runtime.h>
#include <cuda_fp16.h>
#include <mma.h>
#include <cstdint>

using namespace nvcuda;

#define B_TOK 1024
#define DDIM  768
#define FDIM  24576
#define KTOP  64
#define CONN  32

// ---------------- scratch (device globals: no allocation allowed) ----------------
// Device globals are ONLY referenced from device code (host-side &global is the
// host shadow symbol — the bug behind rounds 4/5/6/8/11).
__device__ float g_pre[(size_t)B_TOK * FDIM];
__device__ float g_WupT[(size_t)FDIM * DDIM];        // W_dec_up^T   [F, D]
__device__ float g_WdownT[(size_t)FDIM * DDIM];      // W_dec_down^T [F, D]
__device__ __align__(16) __half g_Xh[(size_t)B_TOK * DDIM];
__device__ __align__(16) __half g_Xm[(size_t)B_TOK * DDIM];
__device__ __align__(16) __half g_Wh[(size_t)FDIM * DDIM];
__device__ __align__(16) __half g_Wm[(size_t)FDIM * DDIM];
__device__ float g_upvals[B_TOK * KTOP];
__device__ int   g_upidx[B_TOK * KTOP];
__device__ float g_downvals[B_TOK * KTOP];
__device__ int   g_downidx[B_TOK * KTOP];
__device__ float g_approx[B_TOK * KTOP];

// ---------------- split fp32 -> planar fp16 hi/mid (PROVEN R12) ----------------
__global__ void split_x_kernel(const float* __restrict__ src, const float* __restrict__ b_dec,
                               int n8)
{
    int i = blockIdx.x * blockDim.x + threadIdx.x;
    if (i >= n8) return;
    int col = (i * 8) % DDIM;
    float4 a = ((const float4*)src)[i * 2];
    float4 b = ((const float4*)src)[i * 2 + 1];
    float4 c = *(const float4*)(b_dec + col);
    float4 d = *(const float4*)(b_dec + col + 4);
    float f[8] = {a.x - c.x, a.y - c.y, a.z - c.z, a.w - c.w,
                  b.x - d.x, b.y - d.y, b.z - d.z, b.w - d.w};
    unsigned short hs[8], ms[8];
#pragma unroll
    for (int j = 0; j < 8; j++) {
        float fs = f[j] * 64.f;
        __half h = __float2half_rn(fs);
        hs[j] = __half_as_ushort(h);
        ms[j] = __half_as_ushort(__float2half_rn(fs - __half2float(h)));
    }
    uint4 hv, mv;
    hv.x = hs[0] | ((unsigned)hs[1] << 16); hv.y = hs[2] | ((unsigned)hs[3] << 16);
    hv.z = hs[4] | ((unsigned)hs[5] << 16); hv.w = hs[6] | ((unsigned)hs[7] << 16);
    mv.x = ms[0] | ((unsigned)ms[1] << 16); mv.y = ms[2] | ((unsigned)ms[3] << 16);
    mv.z = ms[4] | ((unsigned)ms[5] << 16); mv.w = ms[6] | ((unsigned)ms[7] << 16);
    ((uint4*)g_Xh)[i] = hv;
    ((uint4*)g_Xm)[i] = mv;
}

__global__ void split_w_kernel(const float* __restrict__ src, int n8)
{
    int i = blockIdx.x * blockDim.x + threadIdx.x;
    if (i >= n8) return;
    float4 a = ((const float4*)src)[i * 2];
    float4 b = ((const float4*)src)[i * 2 + 1];
    float f[8] = {a.x, a.y, a.z, a.w, b.x, b.y, b.z, b.w};
    unsigned short hs[8], ms[8];
#pragma unroll
    for (int j = 0; j < 8; j++) {
        float fs = f[j] * 64.f;
        __half h = __float2half_rn(fs);
        hs[j] = __half_as_ushort(h);
        ms[j] = __half_as_ushort(__float2half_rn(fs - __half2float(h)));
    }
    uint4 hv, mv;
    hv.x = hs[0] | ((unsigned)hs[1] << 16); hv.y = hs[2] | ((unsigned)hs[3] << 16);
    hv.z = hs[4] | ((unsigned)hs[5] << 16); hv.w = hs[6] | ((unsigned)hs[7] << 16);
    mv.x = ms[0] | ((unsigned)ms[1] << 16); mv.y = ms[2] | ((unsigned)ms[3] << 16);
    mv.z = ms[4] | ((unsigned)ms[5] << 16); mv.w = ms[6] | ((unsigned)ms[7] << 16);
    ((uint4*)g_Wh)[i] = hv;
    ((uint4*)g_Wm)[i] = mv;
}

// ---------------- transpose W_dec [D, F] -> [F, D], float4 both sides (PROVEN R14) ----------------
__global__ void transpose_kernel(const float* __restrict__ in, int which)
{
    __shared__ float tile[32][33];
    float* out = (which == 0) ? g_WupT : g_WdownT;
    int f0 = blockIdx.x * 32;
    int d0 = blockIdx.y * 32;
    int t = threadIdx.x;            // 256 threads
    int r = t >> 3, c = t & 7;

    float4 v = *(const float4*)(in + (size_t)(d0 + r) * FDIM + f0 + 4 * c);
    tile[r][4 * c + 0] = v.x;
    tile[r][4 * c + 1] = v.y;
    tile[r][4 * c + 2] = v.z;
    tile[r][4 * c + 3] = v.w;
    __syncthreads();

    float4 o;
    o.x = tile[4 * c + 0][r];
    o.y = tile[4 * c + 1][r];
    o.z = tile[4 * c + 2][r];
    o.w = tile[4 * c + 3][r];
    *(float4*)(out + (size_t)(f0 + r) * DDIM + d0 + 4 * c) = o;
}

// ---------------- WMMA encode GEMM (PROVEN R12 math), stage aliased into planes ----------------
// pre = relu( (1/4096) * [XhWh + XhWm + XmWh] + b_enc )
#define TP2   24                 // halves per SMEM row (48 B)
#define PLANE (128 * TP2)        // halves per plane (6144 B)
#define SP    24                 // staging pitch in floats

__global__ __launch_bounds__(256, 2)
void gemm_wmma_kernel(const float* __restrict__ b_enc)
{
    __shared__ __align__(16) __half splanes[4 * PLANE];   // 24576 B; stage aliased post-loop

    __half* Ah = splanes;
    __half* Am = splanes + PLANE;
    __half* Wh = splanes + 2 * PLANE;
    __half* Wm = splanes + 3 * PLANE;

    const int tid = threadIdx.x;
    const int wid = tid >> 5, lane = tid & 31;
    const int wm = wid >> 2, wn = wid & 3;     // warp tile: rows [wm*64,+64), cols [wn*32,+32)
    const int bm = blockIdx.x * 128;           // over B
    const int bn = blockIdx.y * 128;           // over F

    const int lm = tid >> 1, lq = (tid & 1) * 8;   // loader: row lm, halves [lq, lq+8)

    wmma::fragment<wmma::accumulator, 16, 16, 16, float> c[4][2];
#pragma unroll
    for (int mf = 0; mf < 4; mf++)
#pragma unroll
        for (int nf = 0; nf < 2; nf++)
            wmma::fill_fragment(c[mf][nf], 0.f);

    uint4 rxh, rxm, rwh, rwm;   // prefetch registers
    auto load_regs = [&](int k0) {
        size_t xo = (size_t)(bm + lm) * DDIM + k0 + lq;
        size_t wo = (size_t)(bn + lm) * DDIM + k0 + lq;
        rxh = *(const uint4*)(g_Xh + xo);
        rxm = *(const uint4*)(g_Xm + xo);
        rwh = *(const uint4*)(g_Wh + wo);
        rwm = *(const uint4*)(g_Wm + wo);
    };
    auto store_smem = [&]() {
        *(uint4*)(Ah + lm * TP2 + lq) = rxh;
        *(uint4*)(Am + lm * TP2 + lq) = rxm;
        *(uint4*)(Wh + lm * TP2 + lq) = rwh;
        *(uint4*)(Wm + lm * TP2 + lq) = rwm;
    };

    load_regs(0);
    for (int k0 = 0; k0 < DDIM; k0 += 16) {
        store_smem();
        __syncthreads();
        if (k0 + 16 < DDIM) load_regs(k0 + 16);   // overlap next loads with compute

        wmma::fragment<wmma::matrix_a, 16, 16, 16, __half, wmma::row_major> ah[4], am[4];
#pragma unroll
        for (int mf = 0; mf < 4; mf++) {
            wmma::load_matrix_sync(ah[mf], Ah + (wm * 64 + mf * 16) * TP2, TP2);
            wmma::load_matrix_sync(am[mf], Am + (wm * 64 + mf * 16) * TP2, TP2);
        }
#pragma unroll
        for (int nf = 0; nf < 2; nf++) {
            wmma::fragment<wmma::matrix_b, 16, 16, 16, __half, wmma::col_major> bh, bm2;
            wmma::load_matrix_sync(bh,  Wh + (wn * 32 + nf * 16) * TP2, TP2);
            wmma::load_matrix_sync(bm2, Wm + (wn * 32 + nf * 16) * TP2, TP2);
#pragma unroll
            for (int mf = 0; mf < 4; mf++) {
                wmma::mma_sync(c[mf][nf], ah[mf], bh,  c[mf][nf]);
                wmma::mma_sync(c[mf][nf], ah[mf], bm2, c[mf][nf]);
                wmma::mma_sync(c[mf][nf], am[mf], bh,  c[mf][nf]);
            }
        }
        __syncthreads();   // final iteration: all plane reads done -> stage alias safe
    }

    // ---- epilogue (PROVEN R9 pattern), stage aliased into splanes ----
    float* stg = (float*)splanes + wid * 16 * SP;   // 8 warps x 1536 B = 12288 B < 24576 B
    const float inv = 1.f / 4096.f;
    const int r2 = lane >> 1, cq = (lane & 1) * 8;
#pragma unroll
    for (int mf = 0; mf < 4; mf++) {
#pragma unroll
        for (int nf = 0; nf < 2; nf++) {
            wmma::store_matrix_sync(stg, c[mf][nf], SP, wmma::mem_row_major);
            __syncwarp();
            int grow = bm + wm * 64 + mf * 16 + r2;
            int gcol = bn + wn * 32 + nf * 16 + cq;
            float4 s0 = *(const float4*)(stg + r2 * SP + cq);
            float4 s1 = *(const float4*)(stg + r2 * SP + cq + 4);
            float4 o0, o1;
            o0.x = fmaxf(s0.x * inv + b_enc[gcol + 0], 0.f);
            o0.y = fmaxf(s0.y * inv + b_enc[gcol + 1], 0.f);
            o0.z = fmaxf(s0.z * inv + b_enc[gcol + 2], 0.f);
            o0.w = fmaxf(s0.w * inv + b_enc[gcol + 3], 0.f);
            o1.x = fmaxf(s1.x * inv + b_enc[gcol + 4], 0.f);
            o1.y = fmaxf(s1.y * inv + b_enc[gcol + 5], 0.f);
            o1.z = fmaxf(s1.z * inv + b_enc[gcol + 6], 0.f);
            o1.w = fmaxf(s1.w * inv + b_enc[gcol + 7], 0.f);
            *(float4*)(g_pre + (size_t)grow * FDIM + gcol)     = o0;
            *(float4*)(g_pre + (size_t)grow * FDIM + gcol + 4) = o1;
            __syncwarp();
        }
    }
}

// ---------------- exact top-64 radix select: 2 row-passes + register candidate cache ----------------
#define CAPW 8
#define CAPC 8
__global__ void topk_select_kernel(int which)
{
    const int b = blockIdx.x, t = threadIdx.x;   // 512 threads, 12 float4 each
    const float4* row4 = (const float4*)(g_pre + (size_t)b * FDIM);
    __shared__ int   hist[2048];
    __shared__ int   sc[512];
    __shared__ int   sc2[512];
    __shared__ int   s_bstar, s_nabove, s_ncand;
    __shared__ int   cidx[1024];
    __shared__ float cval[1024];

    // pass 1: histogram over top-11 bits (positives only)
    for (int i = t; i < 2048; i += 512) hist[i] = 0;
    __syncthreads();
    for (int j = 0; j < 12; j++) {
        float4 v = row4[t + (j << 9)];
        if (v.x > 0.f) atomicAdd(&hist[__float_as_uint(v.x) >> 21], 1);
        if (v.y > 0.f) atomicAdd(&hist[__float_as_uint(v.y) >> 21], 1);
        if (v.z > 0.f) atomicAdd(&hist[__float_as_uint(v.z) >> 21], 1);
        if (v.w > 0.f) atomicAdd(&hist[__float_as_uint(v.w) >> 21], 1);
    }
    __syncthreads();
    {
        int s = 0;
#pragma unroll
        for (int i = 0; i < 4; i++) s += hist[t * 4 + i];
        sc[t] = s;
    }
    __syncthreads();
    if (t == 0) {
        int cum = 0, bstar = 0, nab = 0;
        bool found = false;
        for (int s = 511; s >= 0 && !found; s--) {
            int sv = sc[s];
            if (sv == 0) continue;
            if (cum + sv >= KTOP) {
                for (int bi = s * 4 + 3; bi >= s * 4; bi--) {
                    int h = hist[bi];
                    if (cum + h >= KTOP) { bstar = bi; nab = cum; found = true; break; }
                    cum += h;
                }
            } else cum += sv;
        }
        if (!found) { bstar = 0; nab = cum; }
        s_bstar = bstar; s_nabove = nab;
    }
    __syncthreads();
    const unsigned bstar = (unsigned)s_bstar;
    const int nabove = s_nabove;

    float* ov = ((which == 0) ? g_upvals : g_downvals) + b * KTOP;
    int*   oi = ((which == 0) ? g_upidx  : g_downidx)  + b * KTOP;

    // pass 2: count AND cache candidates in registers (overflow -> fallback re-read)
    int cnt = 0, ccnt = 0;
    int   widx_l[CAPW]; float wval_l[CAPW];
    int   cidx_l[CAPC]; float cval_l[CAPC];
    for (int j = 0; j < 12; j++) {
        int base = (t + (j << 9)) * 4;
        float4 v = row4[t + (j << 9)];
        float vv[4] = {v.x, v.y, v.z, v.w};
#pragma unroll
        for (int cc2 = 0; cc2 < 4; cc2++) {
            if (vv[cc2] > 0.f) {
                unsigned bin = __float_as_uint(vv[cc2]) >> 21;
                if (bin > bstar) {
                    if (cnt < CAPW) { widx_l[cnt] = base + cc2; wval_l[cnt] = vv[cc2]; }
                    cnt++;
                } else if (bin == bstar) {
                    if (ccnt < CAPC) { cidx_l[ccnt] = base + cc2; cval_l[ccnt] = vv[cc2]; }
                    ccnt++;
                }
            }
        }
    }
    sc[t] = cnt; sc2[t] = ccnt;
    __syncthreads();
    for (int o = 1; o < 512; o <<= 1) {
        int v1 = (t >= o) ? sc[t - o] : 0;
        int v2 = (t >= o) ? sc2[t - o] : 0;
        __syncthreads();
        sc[t] += v1; sc2[t] += v2;
        __syncthreads();
    }
    if (t == 511) s_ncand = (sc2[511] < 1024) ? sc2[511] : 1024;

    // pass 3: write from cached registers (or fallback re-read if overflowed)
    {
        int pos = sc[t] - cnt, cpos = sc2[t] - ccnt;
        if (cnt <= CAPW && ccnt <= CAPC) {
            for (int i = 0; i < cnt; i++)  { ov[pos + i] = wval_l[i]; oi[pos + i] = widx_l[i]; }
            for (int i = 0; i < ccnt; i++) {
                if (cpos + i < 1024) { cidx[cpos + i] = cidx_l[i]; cval[cpos + i] = cval_l[i]; }
            }
        } else {
            int left = cnt + ccnt;
            for (int j = 0; j < 12 && left > 0; j++) {
                int base = (t + (j << 9)) * 4;
                float4 v = row4[t + (j << 9)];
                float vv[4] = {v.x, v.y, v.z, v.w};
#pragma unroll
                for (int cc2 = 0; cc2 < 4; cc2++) {
                    if (vv[cc2] > 0.f) {
                        unsigned bin = __float_as_uint(vv[cc2]) >> 21;
                        if (bin > bstar) {
                            ov[pos] = vv[cc2]; oi[pos] = base + cc2; pos++; left--;
                        } else if (bin == bstar) {
                            if (cpos < 1024) { cidx[cpos] = base + cc2; cval[cpos] = vv[cc2]; }
                            cpos++; left--;
                        }
                    }
                }
            }
        }
    }
    __syncthreads();

    // exact remaining selection (value desc, index asc) by warp 0
    if (t < 32) {
        const int need = KTOP - nabove;
        const int ncand = s_ncand;
        for (int r = 0; r < need; r++) {
            float bv = -1.f; int bidx = 0x7fffffff; int bslot = -1;
            for (int i = t; i < ncand; i += 32) {
                int ix = cidx[i];
                if (ix >= 0) {
                    float v = cval[i];
                    if (v > bv || (v == bv && ix < bidx)) { bv = v; bidx = ix; bslot = i; }
                }
            }
#pragma unroll
            for (int o = 16; o > 0; o >>= 1) {
                float v2 = __shfl_down_sync(0xffffffffu, bv, o);
                int   i2 = __shfl_down_sync(0xffffffffu, bidx, o);
                int   s2 = __shfl_down_sync(0xffffffffu, bslot, o);
                if (v2 > bv || (v2 == bv && i2 < bidx)) { bv = v2; bidx = i2; bslot = s2; }
            }
            bv = __shfl_sync(0xffffffffu, bv, 0);
            bidx = __shfl_sync(0xffffffffu, bidx, 0);
            bslot = __shfl_sync(0xffffffffu, bslot, 0);
            if (t == 0 && bslot >= 0) {
                ov[nabove + r] = bv; oi[nabove + r] = bidx; cidx[bslot] = -1;
            }
            __syncwarp();
        }
    }
}

// ---------------- contributions: approx_acts[b,kd] (PROVEN) ----------------
__global__ void contrib_kernel(const int* __restrict__ conn,
                               const float* __restrict__ W_enc_down)
{
    const int b = blockIdx.x;
    const int w = threadIdx.x >> 5, lane = threadIdx.x & 31;
    __shared__ int   s_ui[KTOP];
    __shared__ float s_uv[KTOP];
    if (threadIdx.x < KTOP) {
        s_ui[threadIdx.x] = g_upidx[b * KTOP + threadIdx.x];
        s_uv[threadIdx.x] = g_upvals[b * KTOP + threadIdx.x];
    }
    __syncthreads();

    for (int kd = w; kd < KTOP; kd += 8) {
        int fd = g_downidx[b * KTOP + kd];
        int ci = conn[(size_t)fd * CONN + lane];

        float partial = 0.f;
        bool loaded = false;
        float er[24];
        for (int ku = 0; ku < KTOP; ku++) {
            int fu = s_ui[ku];
            unsigned m = __ballot_sync(0xffffffffu, ci == fu);
            if (m) {
                if (!loaded) {
#pragma unroll
                    for (int i = 0; i < 24; i++)
                        er[i] = W_enc_down[(size_t)fd * DDIM + lane + i * 32];
                    loaded = true;
                }
                float cntf = (float)__popc(m);
                const float* up = g_WupT + (size_t)fu * DDIM + lane;
                float dot = 0.f;
#pragma unroll
                for (int i = 0; i < 24; i++) dot += er[i] * up[i * 32];
                partial += dot * cntf * s_uv[ku];
            }
        }
#pragma unroll
        for (int o = 16; o > 0; o >>= 1)
            partial += __shfl_down_sync(0xffffffffu, partial, o);
        if (lane == 0) g_approx[b * KTOP + kd] = partial;
    }
}

// ---------------- sparse decode (PROVEN) ----------------
__global__ void recon_kernel(int which, const float* __restrict__ b_dec, float* __restrict__ out)
{
    const int b = blockIdx.x;
    const int t = threadIdx.x;  // 256
    __shared__ float sv[KTOP];
    __shared__ int   si[KTOP];
    if (t < KTOP) {
        if (which == 0) { sv[t] = g_upvals[b * KTOP + t]; si[t] = g_upidx[b * KTOP + t]; }
        else            { sv[t] = g_approx[b * KTOP + t]; si[t] = g_downidx[b * KTOP + t]; }
    }
    __syncthreads();
    const float* WT = (which == 0) ? g_WupT : g_WdownT;

    float a0 = b_dec[t], a1 = b_dec[t + 256], a2 = b_dec[t + 512];
    for (int k = 0; k < KTOP; k++) {
        const float* p = WT + (size_t)si[k] * DDIM + t;
        float v = sv[k];
        a0 += v * p[0];
        a1 += v * p[256];
        a2 += v * p[512];
    }
    size_t o = (size_t)b * DDIM + t;
    out[o]       = a0;
    out[o + 256] = a1;
    out[o + 512] = a2;
}

// ---------------- launch ----------------
extern "C" void kernel_launch(void* const* d_in, const int* in_sizes, int n_in,
                              void* d_out, int out_size)
{
    (void)in_sizes; (void)n_in; (void)out_size;
    const float* x_up       = (const float*)d_in[0];
    const float* x_down     = (const float*)d_in[1];
    const float* W_enc_up   = (const float*)d_in[2];
    const float* b_enc_up   = (const float*)d_in[3];
    const float* W_dec_up   = (const float*)d_in[4];
    const float* b_dec_up   = (const float*)d_in[5];
    const float* W_enc_down = (const float*)d_in[6];
    const float* b_enc_down = (const float*)d_in[7];
    const float* W_dec_down = (const float*)d_in[8];
    const float* b_dec_down = (const float*)d_in[9];
    const int*   connections = (const int*)d_in[10];
    float* out = (float*)d_out;

    const int n8w = FDIM * DDIM / 8;   // 2359296
    const int n8x = B_TOK * DDIM / 8;  // 98304
    dim3 gemm_grid(B_TOK / 128, FDIM / 128);   // x: B tiles (8), y: F tiles (192)
    dim3 tr_grid(FDIM / 32, DDIM / 32);

    // ---- upstream ----
    split_w_kernel<<<n8w / 512, 512>>>(W_enc_up, n8w);
    split_x_kernel<<<n8x / 512, 512>>>(x_up, b_dec_up, n8x);
    gemm_wmma_kernel<<<gemm_grid, 256>>>(b_enc_up);
    topk_select_kernel<<<B_TOK, 512>>>(0);
    transpose_kernel<<<tr_grid, 256>>>(W_dec_up, 0);
    recon_kernel<<<B_TOK, 256>>>(0, b_dec_up, out);

    // ---- downstream ----
    split_w_kernel<<<n8w / 512, 512>>>(W_enc_down, n8w);
    split_x_kernel<<<n8x / 512, 512>>>(x_down, b_dec_down, n8x);
    gemm_wmma_kernel<<<gemm_grid, 256>>>(b_enc_down);
    topk_select_kernel<<<B_TOK, 512>>>(1);
    transpose_kernel<<<tr_grid, 256>>>(W_dec_down, 1);
    contrib_kernel<<<B_TOK, 256>>>(connections, W_enc_down);
    recon_kernel<<<B_TOK, 256>>>(1, b_dec_down, out + (size_t)B_TOK * DDIM);
}

// round 17
// speedup vs baseline: 1.1211x; 1.0487x over previous
#include <cuda_runtime.h>
#include <cuda_fp16.h>
#include <mma.h>
#include <cstdint>

using namespace nvcuda;

#define B_TOK 1024
#define DDIM  768
#define FDIM  24576
#define KTOP  64
#define CONN  32

// ---------------- scratch (device globals: no allocation allowed) ----------------
// Device globals are ONLY referenced from device code (host-side &global is the
// host shadow symbol — the bug behind rounds 4/5/6/8/11).
__device__ float g_pre[(size_t)B_TOK * FDIM];
__device__ float g_WupT[(size_t)FDIM * DDIM];        // W_dec_up^T   [F, D]
__device__ float g_WdownT[(size_t)FDIM * DDIM];      // W_dec_down^T [F, D]
__device__ __align__(16) __half g_Xh[(size_t)B_TOK * DDIM];
__device__ __align__(16) __half g_Xm[(size_t)B_TOK * DDIM];
__device__ __align__(16) __half g_Wh[(size_t)FDIM * DDIM];
__device__ __align__(16) __half g_Wm[(size_t)FDIM * DDIM];
__device__ float g_upvals[B_TOK * KTOP];
__device__ int   g_upidx[B_TOK * KTOP];
__device__ float g_downvals[B_TOK * KTOP];
__device__ int   g_downidx[B_TOK * KTOP];
__device__ float g_approx[B_TOK * KTOP];

// ---------------- split fp32 -> planar fp16 hi/mid (PROVEN R12) ----------------
__global__ void split_x_kernel(const float* __restrict__ src, const float* __restrict__ b_dec,
                               int n8)
{
    int i = blockIdx.x * blockDim.x + threadIdx.x;
    if (i >= n8) return;
    int col = (i * 8) % DDIM;
    float4 a = ((const float4*)src)[i * 2];
    float4 b = ((const float4*)src)[i * 2 + 1];
    float4 c = *(const float4*)(b_dec + col);
    float4 d = *(const float4*)(b_dec + col + 4);
    float f[8] = {a.x - c.x, a.y - c.y, a.z - c.z, a.w - c.w,
                  b.x - d.x, b.y - d.y, b.z - d.z, b.w - d.w};
    unsigned short hs[8], ms[8];
#pragma unroll
    for (int j = 0; j < 8; j++) {
        float fs = f[j] * 64.f;
        __half h = __float2half_rn(fs);
        hs[j] = __half_as_ushort(h);
        ms[j] = __half_as_ushort(__float2half_rn(fs - __half2float(h)));
    }
    uint4 hv, mv;
    hv.x = hs[0] | ((unsigned)hs[1] << 16); hv.y = hs[2] | ((unsigned)hs[3] << 16);
    hv.z = hs[4] | ((unsigned)hs[5] << 16); hv.w = hs[6] | ((unsigned)hs[7] << 16);
    mv.x = ms[0] | ((unsigned)ms[1] << 16); mv.y = ms[2] | ((unsigned)ms[3] << 16);
    mv.z = ms[4] | ((unsigned)ms[5] << 16); mv.w = ms[6] | ((unsigned)ms[7] << 16);
    ((uint4*)g_Xh)[i] = hv;
    ((uint4*)g_Xm)[i] = mv;
}

__global__ void split_w_kernel(const float* __restrict__ src, int n8)
{
    int i = blockIdx.x * blockDim.x + threadIdx.x;
    if (i >= n8) return;
    float4 a = ((const float4*)src)[i * 2];
    float4 b = ((const float4*)src)[i * 2 + 1];
    float f[8] = {a.x, a.y, a.z, a.w, b.x, b.y, b.z, b.w};
    unsigned short hs[8], ms[8];
#pragma unroll
    for (int j = 0; j < 8; j++) {
        float fs = f[j] * 64.f;
        __half h = __float2half_rn(fs);
        hs[j] = __half_as_ushort(h);
        ms[j] = __half_as_ushort(__float2half_rn(fs - __half2float(h)));
    }
    uint4 hv, mv;
    hv.x = hs[0] | ((unsigned)hs[1] << 16); hv.y = hs[2] | ((unsigned)hs[3] << 16);
    hv.z = hs[4] | ((unsigned)hs[5] << 16); hv.w = hs[6] | ((unsigned)hs[7] << 16);
    mv.x = ms[0] | ((unsigned)ms[1] << 16); mv.y = ms[2] | ((unsigned)ms[3] << 16);
    mv.z = ms[4] | ((unsigned)ms[5] << 16); mv.w = ms[6] | ((unsigned)ms[7] << 16);
    ((uint4*)g_Wh)[i] = hv;
    ((uint4*)g_Wm)[i] = mv;
}

// ---------------- transpose W_dec [D, F] -> [F, D], float4 both sides (PROVEN R14) ----------------
__global__ void transpose_kernel(const float* __restrict__ in, int which)
{
    __shared__ float tile[32][33];
    float* out = (which == 0) ? g_WupT : g_WdownT;
    int f0 = blockIdx.x * 32;
    int d0 = blockIdx.y * 32;
    int t = threadIdx.x;            // 256 threads
    int r = t >> 3, c = t & 7;

    float4 v = *(const float4*)(in + (size_t)(d0 + r) * FDIM + f0 + 4 * c);
    tile[r][4 * c + 0] = v.x;
    tile[r][4 * c + 1] = v.y;
    tile[r][4 * c + 2] = v.z;
    tile[r][4 * c + 3] = v.w;
    __syncthreads();

    float4 o;
    o.x = tile[4 * c + 0][r];
    o.y = tile[4 * c + 1][r];
    o.z = tile[4 * c + 2][r];
    o.w = tile[4 * c + 3][r];
    *(float4*)(out + (size_t)(f0 + r) * DDIM + d0 + 4 * c) = o;
}

// ---------------- WMMA encode GEMM (PROVEN R16: R12 math + stage alias) ----------------
// pre = relu( (1/4096) * [XhWh + XhWm + XmWh] + b_enc )
#define TP2   24                 // halves per SMEM row (48 B)
#define PLANE (128 * TP2)        // halves per plane (6144 B)
#define SP    24                 // staging pitch in floats

__global__ __launch_bounds__(256, 2)
void gemm_wmma_kernel(const float* __restrict__ b_enc)
{
    __shared__ __align__(16) __half splanes[4 * PLANE];   // 24576 B; stage aliased post-loop

    __half* Ah = splanes;
    __half* Am = splanes + PLANE;
    __half* Wh = splanes + 2 * PLANE;
    __half* Wm = splanes + 3 * PLANE;

    const int tid = threadIdx.x;
    const int wid = tid >> 5, lane = tid & 31;
    const int wm = wid >> 2, wn = wid & 3;     // warp tile: rows [wm*64,+64), cols [wn*32,+32)
    const int bm = blockIdx.x * 128;           // over B
    const int bn = blockIdx.y * 128;           // over F

    const int lm = tid >> 1, lq = (tid & 1) * 8;   // loader: row lm, halves [lq, lq+8)

    wmma::fragment<wmma::accumulator, 16, 16, 16, float> c[4][2];
#pragma unroll
    for (int mf = 0; mf < 4; mf++)
#pragma unroll
        for (int nf = 0; nf < 2; nf++)
            wmma::fill_fragment(c[mf][nf], 0.f);

    uint4 rxh, rxm, rwh, rwm;   // prefetch registers
    auto load_regs = [&](int k0) {
        size_t xo = (size_t)(bm + lm) * DDIM + k0 + lq;
        size_t wo = (size_t)(bn + lm) * DDIM + k0 + lq;
        rxh = *(const uint4*)(g_Xh + xo);
        rxm = *(const uint4*)(g_Xm + xo);
        rwh = *(const uint4*)(g_Wh + wo);
        rwm = *(const uint4*)(g_Wm + wo);
    };
    auto store_smem = [&]() {
        *(uint4*)(Ah + lm * TP2 + lq) = rxh;
        *(uint4*)(Am + lm * TP2 + lq) = rxm;
        *(uint4*)(Wh + lm * TP2 + lq) = rwh;
        *(uint4*)(Wm + lm * TP2 + lq) = rwm;
    };

    load_regs(0);
    for (int k0 = 0; k0 < DDIM; k0 += 16) {
        store_smem();
        __syncthreads();
        if (k0 + 16 < DDIM) load_regs(k0 + 16);   // overlap next loads with compute

        wmma::fragment<wmma::matrix_a, 16, 16, 16, __half, wmma::row_major> ah[4], am[4];
#pragma unroll
        for (int mf = 0; mf < 4; mf++) {
            wmma::load_matrix_sync(ah[mf], Ah + (wm * 64 + mf * 16) * TP2, TP2);
            wmma::load_matrix_sync(am[mf], Am + (wm * 64 + mf * 16) * TP2, TP2);
        }
#pragma unroll
        for (int nf = 0; nf < 2; nf++) {
            wmma::fragment<wmma::matrix_b, 16, 16, 16, __half, wmma::col_major> bh, bm2;
            wmma::load_matrix_sync(bh,  Wh + (wn * 32 + nf * 16) * TP2, TP2);
            wmma::load_matrix_sync(bm2, Wm + (wn * 32 + nf * 16) * TP2, TP2);
#pragma unroll
            for (int mf = 0; mf < 4; mf++) {
                wmma::mma_sync(c[mf][nf], ah[mf], bh,  c[mf][nf]);
                wmma::mma_sync(c[mf][nf], ah[mf], bm2, c[mf][nf]);
                wmma::mma_sync(c[mf][nf], am[mf], bh,  c[mf][nf]);
            }
        }
        __syncthreads();   // final iteration: all plane reads done -> stage alias safe
    }

    // ---- epilogue (PROVEN), stage aliased into splanes ----
    float* stg = (float*)splanes + wid * 16 * SP;
    const float inv = 1.f / 4096.f;
    const int r2 = lane >> 1, cq = (lane & 1) * 8;
#pragma unroll
    for (int mf = 0; mf < 4; mf++) {
#pragma unroll
        for (int nf = 0; nf < 2; nf++) {
            wmma::store_matrix_sync(stg, c[mf][nf], SP, wmma::mem_row_major);
            __syncwarp();
            int grow = bm + wm * 64 + mf * 16 + r2;
            int gcol = bn + wn * 32 + nf * 16 + cq;
            float4 s0 = *(const float4*)(stg + r2 * SP + cq);
            float4 s1 = *(const float4*)(stg + r2 * SP + cq + 4);
            float4 o0, o1;
            o0.x = fmaxf(s0.x * inv + b_enc[gcol + 0], 0.f);
            o0.y = fmaxf(s0.y * inv + b_enc[gcol + 1], 0.f);
            o0.z = fmaxf(s0.z * inv + b_enc[gcol + 2], 0.f);
            o0.w = fmaxf(s0.w * inv + b_enc[gcol + 3], 0.f);
            o1.x = fmaxf(s1.x * inv + b_enc[gcol + 4], 0.f);
            o1.y = fmaxf(s1.y * inv + b_enc[gcol + 5], 0.f);
            o1.z = fmaxf(s1.z * inv + b_enc[gcol + 6], 0.f);
            o1.w = fmaxf(s1.w * inv + b_enc[gcol + 7], 0.f);
            *(float4*)(g_pre + (size_t)grow * FDIM + gcol)     = o0;
            *(float4*)(g_pre + (size_t)grow * FDIM + gcol + 4) = o1;
            __syncwarp();
        }
    }
}

// ---------------- exact top-64 radix select: shuffle scans + parallel bstar ----------------
#define CAPW 8
#define CAPC 8

static __device__ __forceinline__ int warpscan_incl(int v) {
    int lane = threadIdx.x & 31;
#pragma unroll
    for (int o = 1; o < 32; o <<= 1) {
        int n = __shfl_up_sync(0xffffffffu, v, o);
        if (lane >= o) v += n;
    }
    return v;
}
// block-wide inclusive scan over 512 threads (2 syncthreads); wsum = shared[16]
static __device__ __forceinline__ int blockscan_incl(int v, int* wsum) {
    int t = threadIdx.x, lane = t & 31, w = t >> 5;
    int sv = warpscan_incl(v);
    if (lane == 31) wsum[w] = sv;
    __syncthreads();
    if (w == 0) {
        int s = (lane < 16) ? wsum[lane] : 0;
        s = warpscan_incl(s);
        if (lane < 16) wsum[lane] = s;
    }
    __syncthreads();
    return sv + ((w > 0) ? wsum[w - 1] : 0);
}

__global__ void topk_select_kernel(int which)
{
    const int b = blockIdx.x, t = threadIdx.x;   // 512 threads, 12 float4 each
    const float4* row4 = (const float4*)(g_pre + (size_t)b * FDIM);
    __shared__ int   hist[2048];
    __shared__ int   wsum[16];
    __shared__ int   s_bstar, s_nabove, s_ncand, s_total;
    __shared__ int   cidx[1024];
    __shared__ float cval[1024];

    // pass 1: histogram over top-11 bits (positives only)
    for (int i = t; i < 2048; i += 512) hist[i] = 0;
    __syncthreads();
    for (int j = 0; j < 12; j++) {
        float4 v = row4[t + (j << 9)];
        if (v.x > 0.f) atomicAdd(&hist[__float_as_uint(v.x) >> 21], 1);
        if (v.y > 0.f) atomicAdd(&hist[__float_as_uint(v.y) >> 21], 1);
        if (v.z > 0.f) atomicAdd(&hist[__float_as_uint(v.z) >> 21], 1);
        if (v.w > 0.f) atomicAdd(&hist[__float_as_uint(v.w) >> 21], 1);
    }
    __syncthreads();

    // coarse sums (4 bins per thread) + parallel bstar via suffix crossing
    int coarse = hist[t * 4] + hist[t * 4 + 1] + hist[t * 4 + 2] + hist[t * 4 + 3];
    int incl = blockscan_incl(coarse, wsum);
    if (t == 511) {
        s_total = incl;
        if (incl < KTOP) { s_bstar = 0; s_nabove = incl; }  // degenerate fallback
    }
    __syncthreads();
    {
        int above = s_total - incl;          // sum of coarse chunks strictly above t
        if (above < KTOP && above + coarse >= KTOP) {   // unique crossing thread
            int cum = above, bstar = t * 4, nab = above;
            for (int bi = t * 4 + 3; bi >= t * 4; bi--) {
                int h = hist[bi];
                if (cum + h >= KTOP) { bstar = bi; nab = cum; break; }
                cum += h;
            }
            s_bstar = bstar; s_nabove = nab;
        }
    }
    __syncthreads();
    const unsigned bstar = (unsigned)s_bstar;
    const int nabove = s_nabove;

    float* ov = ((which == 0) ? g_upvals : g_downvals) + b * KTOP;
    int*   oi = ((which == 0) ? g_upidx  : g_downidx)  + b * KTOP;

    // pass 2: count AND cache candidates in registers (overflow -> fallback re-read)
    int cnt = 0, ccnt = 0;
    int   widx_l[CAPW]; float wval_l[CAPW];
    int   cidx_l[CAPC]; float cval_l[CAPC];
    for (int j = 0; j < 12; j++) {
        int base = (t + (j << 9)) * 4;
        float4 v = row4[t + (j << 9)];
        float vv[4] = {v.x, v.y, v.z, v.w};
#pragma unroll
        for (int cc2 = 0; cc2 < 4; cc2++) {
            if (vv[cc2] > 0.f) {
                unsigned bin = __float_as_uint(vv[cc2]) >> 21;
                if (bin > bstar) {
                    if (cnt < CAPW) { widx_l[cnt] = base + cc2; wval_l[cnt] = vv[cc2]; }
                    cnt++;
                } else if (bin == bstar) {
                    if (ccnt < CAPC) { cidx_l[ccnt] = base + cc2; cval_l[ccnt] = vv[cc2]; }
                    ccnt++;
                }
            }
        }
    }
    // fused dual scan: pack (cnt, ccnt) — both block totals <= 24576 < 2^16
    int packed = (cnt << 16) | ccnt;
    int pincl = blockscan_incl(packed, wsum);
    if (t == 511) {
        int ctot = pincl & 0xffff;
        s_ncand = (ctot < 1024) ? ctot : 1024;
    }
    int pos  = ((pincl >> 16) & 0xffff) - cnt;
    int cpos = (pincl & 0xffff) - ccnt;

    // pass 3: write from cached registers (or fallback re-read if overflowed)
    if (cnt <= CAPW && ccnt <= CAPC) {
        for (int i = 0; i < cnt; i++)  { ov[pos + i] = wval_l[i]; oi[pos + i] = widx_l[i]; }
        for (int i = 0; i < ccnt; i++) {
            if (cpos + i < 1024) { cidx[cpos + i] = cidx_l[i]; cval[cpos + i] = cval_l[i]; }
        }
    } else {
        int left = cnt + ccnt;
        for (int j = 0; j < 12 && left > 0; j++) {
            int base = (t + (j << 9)) * 4;
            float4 v = row4[t + (j << 9)];
            float vv[4] = {v.x, v.y, v.z, v.w};
#pragma unroll
            for (int cc2 = 0; cc2 < 4; cc2++) {
                if (vv[cc2] > 0.f) {
                    unsigned bin = __float_as_uint(vv[cc2]) >> 21;
                    if (bin > bstar) {
                        ov[pos] = vv[cc2]; oi[pos] = base + cc2; pos++; left--;
                    } else if (bin == bstar) {
                        if (cpos < 1024) { cidx[cpos] = base + cc2; cval[cpos] = vv[cc2]; }
                        cpos++; left--;
                    }
                }
            }
        }
    }
    __syncthreads();

    // exact remaining selection (value desc, index asc) by warp 0
    if (t < 32) {
        const int need = KTOP - nabove;
        const int ncand = s_ncand;
        for (int r = 0; r < need; r++) {
            float bv = -1.f; int bidx = 0x7fffffff; int bslot = -1;
            for (int i = t; i < ncand; i += 32) {
                int ix = cidx[i];
                if (ix >= 0) {
                    float v = cval[i];
                    if (v > bv || (v == bv && ix < bidx)) { bv = v; bidx = ix; bslot = i; }
                }
            }
#pragma unroll
            for (int o = 16; o > 0; o >>= 1) {
                float v2 = __shfl_down_sync(0xffffffffu, bv, o);
                int   i2 = __shfl_down_sync(0xffffffffu, bidx, o);
                int   s2 = __shfl_down_sync(0xffffffffu, bslot, o);
                if (v2 > bv || (v2 == bv && i2 < bidx)) { bv = v2; bidx = i2; bslot = s2; }
            }
            bv = __shfl_sync(0xffffffffu, bv, 0);
            bidx = __shfl_sync(0xffffffffu, bidx, 0);
            bslot = __shfl_sync(0xffffffffu, bslot, 0);
            if (t == 0 && bslot >= 0) {
                ov[nabove + r] = bv; oi[nabove + r] = bidx; cidx[bslot] = -1;
            }
            __syncwarp();
        }
    }
}

// ---------------- contributions: approx_acts[b,kd] (PROVEN) ----------------
__global__ void contrib_kernel(const int* __restrict__ conn,
                               const float* __restrict__ W_enc_down)
{
    const int b = blockIdx.x;
    const int w = threadIdx.x >> 5, lane = threadIdx.x & 31;
    __shared__ int   s_ui[KTOP];
    __shared__ float s_uv[KTOP];
    if (threadIdx.x < KTOP) {
        s_ui[threadIdx.x] = g_upidx[b * KTOP + threadIdx.x];
        s_uv[threadIdx.x] = g_upvals[b * KTOP + threadIdx.x];
    }
    __syncthreads();

    for (int kd = w; kd < KTOP; kd += 8) {
        int fd = g_downidx[b * KTOP + kd];
        int ci = conn[(size_t)fd * CONN + lane];

        float partial = 0.f;
        bool loaded = false;
        float er[24];
        for (int ku = 0; ku < KTOP; ku++) {
            int fu = s_ui[ku];
            unsigned m = __ballot_sync(0xffffffffu, ci == fu);
            if (m) {
                if (!loaded) {
#pragma unroll
                    for (int i = 0; i < 24; i++)
                        er[i] = W_enc_down[(size_t)fd * DDIM + lane + i * 32];
                    loaded = true;
                }
                float cntf = (float)__popc(m);
                const float* up = g_WupT + (size_t)fu * DDIM + lane;
                float dot = 0.f;
#pragma unroll
                for (int i = 0; i < 24; i++) dot += er[i] * up[i * 32];
                partial += dot * cntf * s_uv[ku];
            }
        }
#pragma unroll
        for (int o = 16; o > 0; o >>= 1)
            partial += __shfl_down_sync(0xffffffffu, partial, o);
        if (lane == 0) g_approx[b * KTOP + kd] = partial;
    }
}

// ---------------- sparse decode (PROVEN) ----------------
__global__ void recon_kernel(int which, const float* __restrict__ b_dec, float* __restrict__ out)
{
    const int b = blockIdx.x;
    const int t = threadIdx.x;  // 256
    __shared__ float sv[KTOP];
    __shared__ int   si[KTOP];
    if (t < KTOP) {
        if (which == 0) { sv[t] = g_upvals[b * KTOP + t]; si[t] = g_upidx[b * KTOP + t]; }
        else            { sv[t] = g_approx[b * KTOP + t]; si[t] = g_downidx[b * KTOP + t]; }
    }
    __syncthreads();
    const float* WT = (which == 0) ? g_WupT : g_WdownT;

    float a0 = b_dec[t], a1 = b_dec[t + 256], a2 = b_dec[t + 512];
    for (int k = 0; k < KTOP; k++) {
        const float* p = WT + (size_t)si[k] * DDIM + t;
        float v = sv[k];
        a0 += v * p[0];
        a1 += v * p[256];
        a2 += v * p[512];
    }
    size_t o = (size_t)b * DDIM + t;
    out[o]       = a0;
    out[o + 256] = a1;
    out[o + 512] = a2;
}

// ---------------- launch ----------------
extern "C" void kernel_launch(void* const* d_in, const int* in_sizes, int n_in,
                              void* d_out, int out_size)
{
    (void)in_sizes; (void)n_in; (void)out_size;
    const float* x_up       = (const float*)d_in[0];
    const float* x_down     = (const float*)d_in[1];
    const float* W_enc_up   = (const float*)d_in[2];
    const float* b_enc_up   = (const float*)d_in[3];
    const float* W_dec_up   = (const float*)d_in[4];
    const float* b_dec_up   = (const float*)d_in[5];
    const float* W_enc_down = (const float*)d_in[6];
    const float* b_enc_down = (const float*)d_in[7];
    const float* W_dec_down = (const float*)d_in[8];
    const float* b_dec_down = (const float*)d_in[9];
    const int*   connections = (const int*)d_in[10];
    float* out = (float*)d_out;

    const int n8w = FDIM * DDIM / 8;   // 2359296
    const int n8x = B_TOK * DDIM / 8;  // 98304
    dim3 gemm_grid(B_TOK / 128, FDIM / 128);   // x: B tiles (8), y: F tiles (192)
    dim3 tr_grid(FDIM / 32, DDIM / 32);

    // ---- upstream ----
    split_w_kernel<<<n8w / 512, 512>>>(W_enc_up, n8w);
    split_x_kernel<<<n8x / 512, 512>>>(x_up, b_dec_up, n8x);
    gemm_wmma_kernel<<<gemm_grid, 256>>>(b_enc_up);
    topk_select_kernel<<<B_TOK, 512>>>(0);
    transpose_kernel<<<tr_grid, 256>>>(W_dec_up, 0);
    recon_kernel<<<B_TOK, 256>>>(0, b_dec_up, out);

    // ---- downstream ----
    split_w_kernel<<<n8w / 512, 512>>>(W_enc_down, n8w);
    split_x_kernel<<<n8x / 512, 512>>>(x_down, b_dec_down, n8x);
    gemm_wmma_kernel<<<gemm_grid, 256>>>(b_enc_down);
    topk_select_kernel<<<B_TOK, 512>>>(1);
    transpose_kernel<<<tr_grid, 256>>>(W_dec_down, 1);
    contrib_kernel<<<B_TOK, 256>>>(connections, W_enc_down);
    recon_kernel<<<B_TOK, 256>>>(1, b_dec_down, out + (size_t)B_TOK * DDIM);
}